// round 1
// baseline (speedup 1.0000x reference)
#include <cuda_runtime.h>

// 64-slot double accumulators for rot / stretch energy (spread atomics across L2 slices)
__device__ double g_rot_acc[64];
__device__ double g_str_acc[64];

__global__ void init_acc_kernel() {
    int i = threadIdx.x;
    if (i < 64) { g_rot_acc[i] = 0.0; g_str_acc[i] = 0.0; }
}

struct HingeOut {
    float d1x, d1y, d2x, d2y;  // dtheta/dv1, dtheta/dv2
    float g;                   // k_eff * (theta - theta_ss)
    float e;                   // 0.5 * k_eff * (theta - theta_ss)^2
};

__device__ __forceinline__ HingeOut hinge_calc(
    float2 a, float2 b, float2 c, float th, int2 B,
    float k_stiff, float k_soft)
{
    float v1x = b.x - a.x, v1y = b.y - a.y;
    float v2x = c.x - b.x, v2y = c.y - b.y;
    float cr = v1x * v2y - v1y * v2x;
    float dt = v1x * v2x + v1y * v2y;
    float theta = atan2f(cr, dt);

    bool m0 = (B.x == 1 && theta > -th) || (B.x == -1 && theta < th);
    bool m1 = (B.y == 1 && theta > -th) || (B.y == -1 && theta < th);
    float keff = (m0 ? k_stiff : k_soft) + (m1 ? k_stiff : k_soft);

    float diff = theta - th;
    HingeOut o;
    o.g = keff * diff;
    o.e = 0.5f * keff * diff * diff;

    float inv = __fdividef(1.0f, cr * cr + dt * dt);
    o.d1x = ( dt * v2y - cr * v2x) * inv;
    o.d1y = (-dt * v2x - cr * v2y) * inv;
    o.d2x = (-dt * v1y - cr * v1x) * inv;
    o.d2y = ( dt * v1x - cr * v1y) * inv;
    return o;
}

__global__ void __launch_bounds__(256)
chain_force_kernel(const float2* __restrict__ pos,
                   const float*  __restrict__ th_ss,
                   const float*  __restrict__ rest,
                   const float*  __restrict__ p_kstiff,
                   const float*  __restrict__ p_ksoft,
                   const float*  __restrict__ p_kstretch,
                   const int2*   __restrict__ buckle,
                   float*        __restrict__ out,
                   int H)
{
    const int N = H + 2;
    const int p = blockIdx.x * blockDim.x + threadIdx.x;
    const bool valid = (p < N);
    const int pc = valid ? p : (N - 1);

    const float k_stiff   = __ldg(p_kstiff);
    const float k_soft    = __ldg(p_ksoft);
    const float k_stretch = __ldg(p_kstretch);

    // neighborhood loads (clamped; unused values guarded by conditions below)
    const float2 P0  = __ldg(&pos[pc]);
    const float2 Pm1 = __ldg(&pos[pc >= 1 ? pc - 1 : 0]);
    const float2 Pm2 = __ldg(&pos[pc >= 2 ? pc - 2 : 0]);
    const float2 Pp1 = __ldg(&pos[pc + 1 < N ? pc + 1 : N - 1]);
    const float2 Pp2 = __ldg(&pos[pc + 2 < N ? pc + 2 : N - 1]);

    float gx = 0.0f, gy = 0.0f;
    float rot_e = 0.0f, str_e = 0.0f;

    // hinge h = p : this point is 'a'. Also owns the hinge's energy term.
    if (valid && p < H) {
        HingeOut o = hinge_calc(P0, Pp1, Pp2, __ldg(&th_ss[p]), __ldg(&buckle[p]),
                                k_stiff, k_soft);
        rot_e = o.e;
        gx -= o.g * o.d1x;
        gy -= o.g * o.d1y;
    }
    // hinge h = p-1 : this point is 'b'
    if (valid && p >= 1 && p - 1 < H) {
        HingeOut o = hinge_calc(Pm1, P0, Pp1, __ldg(&th_ss[p - 1]), __ldg(&buckle[p - 1]),
                                k_stiff, k_soft);
        gx += o.g * (o.d1x - o.d2x);
        gy += o.g * (o.d1y - o.d2y);
    }
    // hinge h = p-2 : this point is 'c'
    if (valid && p >= 2 && p - 2 < H) {
        HingeOut o = hinge_calc(Pm2, Pm1, P0, __ldg(&th_ss[p - 2]), __ldg(&buckle[p - 2]),
                                k_stiff, k_soft);
        gx += o.g * o.d2x;
        gy += o.g * o.d2y;
    }

    // stretch: edge p (tail end); this thread owns edge p's energy term
    if (valid && p <= H) {
        float ex = Pp1.x - P0.x, ey = Pp1.y - P0.y;
        float len = sqrtf(ex * ex + ey * ey);
        float dl = len - __ldg(&rest[p]);
        str_e = 0.5f * k_stretch * dl * dl;
        float c = k_stretch * dl * __fdividef(1.0f, len);
        gx -= c * ex;
        gy -= c * ey;
    }
    // stretch: edge p-1 (head end)
    if (valid && p >= 1) {
        float ex = P0.x - Pm1.x, ey = P0.y - Pm1.y;
        float len = sqrtf(ex * ex + ey * ey);
        float dl = len - __ldg(&rest[p - 1]);
        float c = k_stretch * dl * __fdividef(1.0f, len);
        gx += c * ex;
        gy += c * ey;
    }

    // write force (free mask zeroes coords 0..3 == points 0,1)
    if (valid) {
        float fx = (p < 2) ? 0.0f : -gx;
        float fy = (p < 2) ? 0.0f : -gy;
        out[3 + 2 * p]     = fx;
        out[3 + 2 * p + 1] = fy;
    }

    // -------- block reduction of energies (double) --------
    double r = (double)rot_e;
    double s = (double)str_e;
    #pragma unroll
    for (int off = 16; off > 0; off >>= 1) {
        r += __shfl_down_sync(0xffffffffu, r, off);
        s += __shfl_down_sync(0xffffffffu, s, off);
    }
    __shared__ double sr[8];
    __shared__ double ss[8];
    const int wid  = threadIdx.x >> 5;
    const int lane = threadIdx.x & 31;
    if (lane == 0) { sr[wid] = r; ss[wid] = s; }
    __syncthreads();
    if (threadIdx.x == 0) {
        double rt = 0.0, st = 0.0;
        #pragma unroll
        for (int i = 0; i < 8; i++) { rt += sr[i]; st += ss[i]; }
        int slot = blockIdx.x & 63;
        atomicAdd(&g_rot_acc[slot], rt);
        atomicAdd(&g_str_acc[slot], st);
    }
}

__global__ void finish_kernel(float* __restrict__ out) {
    if (threadIdx.x == 0) {
        double rt = 0.0, st = 0.0;
        #pragma unroll
        for (int i = 0; i < 64; i++) { rt += g_rot_acc[i]; st += g_str_acc[i]; }
        out[0] = (float)(rt + st);
        out[1] = (float)rt;
        out[2] = (float)st;
    }
}

extern "C" void kernel_launch(void* const* d_in, const int* in_sizes, int n_in,
                              void* d_out, int out_size) {
    const float2* pos      = (const float2*)d_in[0];
    const float*  th_ss    = (const float*)d_in[1];
    const float*  rest     = (const float*)d_in[2];
    const float*  kstiff   = (const float*)d_in[3];
    const float*  ksoft    = (const float*)d_in[4];
    const float*  kstretch = (const float*)d_in[5];
    const int2*   buckle   = (const int2*)d_in[6];
    float* out = (float*)d_out;

    const int H = in_sizes[1];      // thetas_ss has H elements
    const int N = H + 2;
    const int threads = 256;
    const int blocks = (N + threads - 1) / threads;

    init_acc_kernel<<<1, 64>>>();
    chain_force_kernel<<<blocks, threads>>>(pos, th_ss, rest, kstiff, ksoft,
                                            kstretch, buckle, out, H);
    finish_kernel<<<1, 32>>>(out);
}